// round 11
// baseline (speedup 1.0000x reference)
#include <cuda_runtime.h>
#include <math.h>

// Problem constants (fixed by the dataset)
#define A_   16
#define SK_  2048
#define SQ_  2048
#define D_   128
#define IDM_ 128
#define RR_  3
// T_ANNEAL = 10, t_ANNEAL = 0

// ---------------------------------------------------------------------------
// Scratch (device global — no allocation allowed)
// Hash codes, padded to float4 per row.  K-codes pre-scaled by 1/R.
// ---------------------------------------------------------------------------
__device__ float4 g_code[2][A_ * SK_];       // [0] = Kc/3, [1] = Qc

// ---------------------------------------------------------------------------
// Kernel 1: fold + code fused, NO gating — each block redundantly computes
// the 128x3 folded projection for its head (L2-hot Wx, ~64KB/block), then
// codes 32 rows with 1 row/warp (proven R6 layout).
// Grid: 2048 blocks = (side, a, chunk-of-32-rows).  Block: 1024 threads.
// ---------------------------------------------------------------------------
__global__ void __launch_bounds__(1024) code_kernel(
        const float* __restrict__ K,  const float* __restrict__ Q,
        const float* __restrict__ Wk, const float* __restrict__ bk,
        const float* __restrict__ Wq, const float* __restrict__ bq,
        const float* __restrict__ W) {
    const int t    = threadIdx.x;
    const int warp = t >> 5;
    const int lane = t & 31;

    const int gr0  = blockIdx.x * 32;            // first global row of block
    const int side = (gr0 >= A_ * SK_) ? 1 : 0;  // uniform per block
    const int row0 = side ? (gr0 - A_ * SK_) : gr0;
    const int a    = row0 >> 11;                 // uniform per block

    const float* X  = side ? Q  : K;
    const float* Wx = side ? Wq : Wk;
    const float* bx = side ? bq : bk;

    // Issue this warp's X row load FIRST — DRAM latency hides the fold below.
    const int row = row0 + warp;
    const float4 x = reinterpret_cast<const float4*>(X)[row * (D_ / 4) + lane];

    __shared__ float Msh[IDM_ * RR_];            // folded M, d-major [d*3+r]
    __shared__ float csh[RR_];

    // Fold: threads 0..383 each compute one M[d][r] = sum_e Wx[e,d]*W[a,e,r].
    // For fixed e, consecutive threads read consecutive d -> coalesced, L2-hot.
    if (t < IDM_ * RR_) {
        const int d = t & 127;
        const int r = t >> 7;
        const float* wcol = W + a * (IDM_ * RR_) + r;   // stride RR_
        float acc = 0.f;
#pragma unroll 16
        for (int e = 0; e < IDM_; e++)
            acc = fmaf(Wx[e * D_ + d], wcol[e * RR_], acc);
        Msh[d * RR_ + r] = acc;
    }

    // Bias fold on warp 12 (t in [384,416)): c[r] = sum_e bx[e]*W[a,e,r].
    if (t >= 384 && t < 416) {
        const int l = t - 384;
        const float* Wa = W + a * (IDM_ * RR_);
        float c0 = 0.f, c1 = 0.f, c2 = 0.f;
#pragma unroll
        for (int e = l; e < IDM_; e += 32) {
            float b = bx[e];
            c0 = fmaf(b, Wa[e * RR_ + 0], c0);
            c1 = fmaf(b, Wa[e * RR_ + 1], c1);
            c2 = fmaf(b, Wa[e * RR_ + 2], c2);
        }
#pragma unroll
        for (int o = 16; o > 0; o >>= 1) {
            c0 += __shfl_xor_sync(0xffffffffu, c0, o);
            c1 += __shfl_xor_sync(0xffffffffu, c1, o);
            c2 += __shfl_xor_sync(0xffffffffu, c2, o);
        }
        if (l == 0) { csh[0] = c0; csh[1] = c1; csh[2] = c2; }
    }
    __syncthreads();

    // Code: 1 row/warp.  Per-lane M slice (d = lane*4..+3, 12 floats).
    const float* M = &Msh[lane * 12];
    float4 m0 = *reinterpret_cast<const float4*>(M);
    float4 m1 = *reinterpret_cast<const float4*>(M + 4);
    float4 m2 = *reinterpret_cast<const float4*>(M + 8);

    float p0 = x.x * m0.x + x.y * m0.w + x.z * m1.z + x.w * m2.y;
    float p1 = x.x * m0.y + x.y * m1.x + x.z * m1.w + x.w * m2.z;
    float p2 = x.x * m0.z + x.y * m1.y + x.z * m2.x + x.w * m2.w;

#pragma unroll
    for (int o = 16; o > 0; o >>= 1) {
        p0 += __shfl_xor_sync(0xffffffffu, p0, o);
        p1 += __shfl_xor_sync(0xffffffffu, p1, o);
        p2 += __shfl_xor_sync(0xffffffffu, p2, o);
    }
    if (lane == 0) {
        float scale = side ? 1.0f : (1.0f / 3.0f);   // fold /R into Kc
        float v0 = tanhf((p0 + csh[0]) * 0.1f) * scale;
        float v1 = tanhf((p1 + csh[1]) * 0.1f) * scale;
        float v2 = tanhf((p2 + csh[2]) * 0.1f) * scale;
        g_code[side][row] = make_float4(v0, v1, v2, 0.f);
    }
}

// ---------------------------------------------------------------------------
// Kernel 2 (R10 version, unchanged): main pass, 16 t-rows x 1024 s-cols.
// ---------------------------------------------------------------------------
__device__ __forceinline__ float pc_fn(const float4 q, const float4 k) {
    float x  = fmaf(q.x, k.x, fmaf(q.y, k.y, q.z * k.z));      // Kc already /3
    float t  = x * x;
    float sg = fmaf(x, fmaf(t, -2.0833333e-5f, 0.025f), 0.5f); // sigmoid(x/10)
    return x * sg;
}

__global__ void __launch_bounds__(256) pc_kernel(float* __restrict__ out) {
    const int a     = blockIdx.z;
    const int tbase = blockIdx.y * 16;
    const int sbase = blockIdx.x * 1024;
    const int tid   = threadIdx.x;

    __shared__ float4 qc_sh[16];
    if (tid < 16)
        qc_sh[tid] = g_code[1][a * SQ_ + tbase + tid];

    const float4* kc = &g_code[0][a * SK_ + sbase + tid * 4];
    const float4 k0 = kc[0];
    const float4 k1 = kc[1];
    const float4 k2 = kc[2];
    const float4 k3 = kc[3];
    __syncthreads();

    float* obase = out + ((size_t)(a * SQ_ + tbase)) * SK_ + (size_t)(sbase + tid * 4);
#pragma unroll 4
    for (int j = 0; j < 16; j++) {
        const float4 q = qc_sh[j];        // broadcast LDS
        float4 o;
        o.x = pc_fn(q, k0);
        o.y = pc_fn(q, k1);
        o.z = pc_fn(q, k2);
        o.w = pc_fn(q, k3);
        *reinterpret_cast<float4*>(obase + (size_t)j * SK_) = o;
    }
}

// ---------------------------------------------------------------------------
// Launch
// ---------------------------------------------------------------------------
extern "C" void kernel_launch(void* const* d_in, const int* in_sizes, int n_in,
                              void* d_out, int out_size) {
    const float* K  = (const float*)d_in[0];
    const float* Q  = (const float*)d_in[1];
    const float* Wk = (const float*)d_in[2];
    const float* bk = (const float*)d_in[3];
    const float* Wq = (const float*)d_in[4];
    const float* bq = (const float*)d_in[5];
    const float* W  = (const float*)d_in[6];
    float* out = (float*)d_out;

    code_kernel<<<(2 * A_ * SK_) / 32, 1024>>>(K, Q, Wk, bk, Wq, bq, W);
    pc_kernel<<<dim3(SK_ / 1024, SQ_ / 16, A_), 256>>>(out);
}

// round 12
// speedup vs baseline: 1.6968x; 1.6968x over previous
#include <cuda_runtime.h>
#include <math.h>

// Problem constants (fixed by the dataset)
#define A_   16
#define SK_  2048
#define SQ_  2048
#define D_   128
#define IDM_ 128
#define RR_  3
// T_ANNEAL = 10, t_ANNEAL = 0

// ---------------------------------------------------------------------------
// Scratch (device globals — no allocation allowed)
// ---------------------------------------------------------------------------
__device__ float  g_M[2][A_ * IDM_ * RR_];   // folded projections
__device__ float  g_c[2][A_ * RR_];          // folded bias projections
__device__ float4 g_code[2][A_ * SK_];       // [0] = Kc/3, [1] = Qc

// ---------------------------------------------------------------------------
// Kernel 1 (R10 version, proven 6.2us): fold Wk/Wq + bias through W[a].
// Grid: 32 blocks = (side, a).  Block: 512 threads = (epart 0..3, d 0..127).
// All 32 Wx loads issued up-front (MLP=32) before the dependent smem phase.
// ---------------------------------------------------------------------------
__global__ void __launch_bounds__(512) prep_kernel(
        const float* __restrict__ Wk, const float* __restrict__ bk,
        const float* __restrict__ Wq, const float* __restrict__ bq,
        const float* __restrict__ W) {
    const int side = blockIdx.x >> 4;        // 0 = K, 1 = Q
    const int a    = blockIdx.x & 15;
    const float* Wx = side ? Wq : Wk;
    const float* bx = side ? bq : bk;

    const int t  = threadIdx.x;
    const int d  = t & 127;
    const int ep = t >> 7;                   // e-partition 0..3

    float w[32];
#pragma unroll
    for (int i = 0; i < 32; i++)
        w[i] = Wx[(ep * 32 + i) * D_ + d];

    __shared__ float Wsh[IDM_ * RR_];        // W[a] : [128,3]
    __shared__ float red[4][IDM_ * RR_];     // partial sums

    for (int i = t; i < IDM_ * RR_; i += 512) Wsh[i] = W[a * IDM_ * RR_ + i];
    __syncthreads();

    float a0 = 0.f, a1 = 0.f, a2 = 0.f;
#pragma unroll
    for (int i = 0; i < 32; i++) {
        int e = ep * 32 + i;
        a0 = fmaf(w[i], Wsh[e * 3 + 0], a0);
        a1 = fmaf(w[i], Wsh[e * 3 + 1], a1);
        a2 = fmaf(w[i], Wsh[e * 3 + 2], a2);
    }
    red[ep][d * 3 + 0] = a0;
    red[ep][d * 3 + 1] = a1;
    red[ep][d * 3 + 2] = a2;
    __syncthreads();

    if (ep == 0) {
        int base = a * (IDM_ * RR_) + d * RR_;
#pragma unroll
        for (int r = 0; r < RR_; r++) {
            int i = d * 3 + r;
            g_M[side][base + r] = red[0][i] + red[1][i] + red[2][i] + red[3][i];
        }
    }

    if (t < 32) {   // bias fold on warp 0
        float c0 = 0.f, c1 = 0.f, c2 = 0.f;
#pragma unroll
        for (int e = t; e < IDM_; e += 32) {
            float b = bx[e];
            c0 = fmaf(b, Wsh[e * 3 + 0], c0);
            c1 = fmaf(b, Wsh[e * 3 + 1], c1);
            c2 = fmaf(b, Wsh[e * 3 + 2], c2);
        }
#pragma unroll
        for (int o = 16; o > 0; o >>= 1) {
            c0 += __shfl_xor_sync(0xffffffffu, c0, o);
            c1 += __shfl_xor_sync(0xffffffffu, c1, o);
            c2 += __shfl_xor_sync(0xffffffffu, c2, o);
        }
        if (t == 0) {
            g_c[side][a * RR_ + 0] = c0;
            g_c[side][a * RR_ + 1] = c1;
            g_c[side][a * RR_ + 2] = c2;
        }
    }
}

// ---------------------------------------------------------------------------
// Kernel 2: hash codes, 4 rows per warp (MLP=4 on the X loads).
// Butterfly reduction leaves full sums in all lanes; lanes 0..3 write rows.
// Grid: 2048 blocks x 256 threads = 16384 warps x 4 rows = 65536 rows.
// ---------------------------------------------------------------------------
__global__ void __launch_bounds__(256) code_kernel(
        const float* __restrict__ K, const float* __restrict__ Q) {
    int warp = (blockIdx.x * blockDim.x + threadIdx.x) >> 5;
    int lane = threadIdx.x & 31;
    int grow0 = warp * 4;                    // 4 consecutive rows, same (side,a)
    int which = (grow0 >= A_ * SK_) ? 1 : 0;
    int row0  = which ? (grow0 - A_ * SK_) : grow0;
    int a     = row0 >> 11;

    const float* X = which ? Q : K;
    // 4 independent row loads in flight
    const float4* Xv = reinterpret_cast<const float4*>(X);
    float4 x0 = Xv[(row0 + 0) * (D_ / 4) + lane];
    float4 x1 = Xv[(row0 + 1) * (D_ / 4) + lane];
    float4 x2 = Xv[(row0 + 2) * (D_ / 4) + lane];
    float4 x3 = Xv[(row0 + 3) * (D_ / 4) + lane];

    const float* M = &g_M[which][a * (IDM_ * RR_) + lane * 12];
    float4 m0 = *reinterpret_cast<const float4*>(M);
    float4 m1 = *reinterpret_cast<const float4*>(M + 4);
    float4 m2 = *reinterpret_cast<const float4*>(M + 8);

    // partial dots: p[row][r]
    float p00 = x0.x * m0.x + x0.y * m0.w + x0.z * m1.z + x0.w * m2.y;
    float p01 = x0.x * m0.y + x0.y * m1.x + x0.z * m1.w + x0.w * m2.z;
    float p02 = x0.x * m0.z + x0.y * m1.y + x0.z * m2.x + x0.w * m2.w;
    float p10 = x1.x * m0.x + x1.y * m0.w + x1.z * m1.z + x1.w * m2.y;
    float p11 = x1.x * m0.y + x1.y * m1.x + x1.z * m1.w + x1.w * m2.z;
    float p12 = x1.x * m0.z + x1.y * m1.y + x1.z * m2.x + x1.w * m2.w;
    float p20 = x2.x * m0.x + x2.y * m0.w + x2.z * m1.z + x2.w * m2.y;
    float p21 = x2.x * m0.y + x2.y * m1.x + x2.z * m1.w + x2.w * m2.z;
    float p22 = x2.x * m0.z + x2.y * m1.y + x2.z * m2.x + x2.w * m2.w;
    float p30 = x3.x * m0.x + x3.y * m0.w + x3.z * m1.z + x3.w * m2.y;
    float p31 = x3.x * m0.y + x3.y * m1.x + x3.z * m1.w + x3.w * m2.z;
    float p32 = x3.x * m0.z + x3.y * m1.y + x3.z * m2.x + x3.w * m2.w;

#pragma unroll
    for (int o = 16; o > 0; o >>= 1) {       // 12 interleaved chains
        p00 += __shfl_xor_sync(0xffffffffu, p00, o);
        p10 += __shfl_xor_sync(0xffffffffu, p10, o);
        p20 += __shfl_xor_sync(0xffffffffu, p20, o);
        p30 += __shfl_xor_sync(0xffffffffu, p30, o);
        p01 += __shfl_xor_sync(0xffffffffu, p01, o);
        p11 += __shfl_xor_sync(0xffffffffu, p11, o);
        p21 += __shfl_xor_sync(0xffffffffu, p21, o);
        p31 += __shfl_xor_sync(0xffffffffu, p31, o);
        p02 += __shfl_xor_sync(0xffffffffu, p02, o);
        p12 += __shfl_xor_sync(0xffffffffu, p12, o);
        p22 += __shfl_xor_sync(0xffffffffu, p22, o);
        p32 += __shfl_xor_sync(0xffffffffu, p32, o);
    }

    // Lanes 0..3 each finish one row (full sums present in every lane).
    if (lane < 4) {
        float s0 = (lane == 0) ? p00 : (lane == 1) ? p10 : (lane == 2) ? p20 : p30;
        float s1 = (lane == 0) ? p01 : (lane == 1) ? p11 : (lane == 2) ? p21 : p31;
        float s2 = (lane == 0) ? p02 : (lane == 1) ? p12 : (lane == 2) ? p22 : p32;
        const float* c = &g_c[which][a * RR_];
        float scale = which ? 1.0f : (1.0f / 3.0f);   // fold /R into Kc
        float v0 = tanhf((s0 + c[0]) * 0.1f) * scale;
        float v1 = tanhf((s1 + c[1]) * 0.1f) * scale;
        float v2 = tanhf((s2 + c[2]) * 0.1f) * scale;
        g_code[which][row0 + lane] = make_float4(v0, v1, v2, 0.f);
    }
}

// ---------------------------------------------------------------------------
// Kernel 3 (R10 version, unchanged): main pass, 16 t-rows x 1024 s-cols.
// ---------------------------------------------------------------------------
__device__ __forceinline__ float pc_fn(const float4 q, const float4 k) {
    float x  = fmaf(q.x, k.x, fmaf(q.y, k.y, q.z * k.z));      // Kc already /3
    float t  = x * x;
    float sg = fmaf(x, fmaf(t, -2.0833333e-5f, 0.025f), 0.5f); // sigmoid(x/10)
    return x * sg;
}

__global__ void __launch_bounds__(256) pc_kernel(float* __restrict__ out) {
    const int a     = blockIdx.z;
    const int tbase = blockIdx.y * 16;
    const int sbase = blockIdx.x * 1024;
    const int tid   = threadIdx.x;

    __shared__ float4 qc_sh[16];
    if (tid < 16)
        qc_sh[tid] = g_code[1][a * SQ_ + tbase + tid];

    const float4* kc = &g_code[0][a * SK_ + sbase + tid * 4];
    const float4 k0 = kc[0];
    const float4 k1 = kc[1];
    const float4 k2 = kc[2];
    const float4 k3 = kc[3];
    __syncthreads();

    float* obase = out + ((size_t)(a * SQ_ + tbase)) * SK_ + (size_t)(sbase + tid * 4);
#pragma unroll 4
    for (int j = 0; j < 16; j++) {
        const float4 q = qc_sh[j];        // broadcast LDS
        float4 o;
        o.x = pc_fn(q, k0);
        o.y = pc_fn(q, k1);
        o.z = pc_fn(q, k2);
        o.w = pc_fn(q, k3);
        *reinterpret_cast<float4*>(obase + (size_t)j * SK_) = o;
    }
}

// ---------------------------------------------------------------------------
// Launch
// ---------------------------------------------------------------------------
extern "C" void kernel_launch(void* const* d_in, const int* in_sizes, int n_in,
                              void* d_out, int out_size) {
    const float* K  = (const float*)d_in[0];
    const float* Q  = (const float*)d_in[1];
    const float* Wk = (const float*)d_in[2];
    const float* bk = (const float*)d_in[3];
    const float* Wq = (const float*)d_in[4];
    const float* bq = (const float*)d_in[5];
    const float* W  = (const float*)d_in[6];
    float* out = (float*)d_out;

    prep_kernel<<<2 * A_, 512>>>(Wk, bk, Wq, bq, W);
    code_kernel<<<(2 * A_ * SK_) / 32, 256>>>(K, Q);
    pc_kernel<<<dim3(SK_ / 1024, SQ_ / 16, A_), 256>>>(out);
}

// round 13
// speedup vs baseline: 1.7207x; 1.0141x over previous
#include <cuda_runtime.h>
#include <math.h>

// Problem constants (fixed by the dataset)
#define A_   16
#define SK_  2048
#define SQ_  2048
#define D_   128
#define IDM_ 128
#define RR_  3
// T_ANNEAL = 10, t_ANNEAL = 0

// ---------------------------------------------------------------------------
// Scratch (device globals — no allocation allowed)
// ---------------------------------------------------------------------------
__device__ float  g_M[2][A_ * IDM_ * RR_];   // folded projections
__device__ float  g_c[2][A_ * RR_];          // folded bias projections
__device__ float4 g_code[2][A_ * SK_];       // [0] = Kc/3, [1] = Qc

// ---------------------------------------------------------------------------
// Kernel 1: fold Wk/Wq + bias through W[a].
// Grid: 32 blocks = (side, a).  Block: 512 threads = (epart 0..3, d 0..127).
// __launch_bounds__(512, 1): only 32 blocks exist chip-wide, so occupancy is
// irrelevant — allow up to 128 regs so the 32-load prefetch stays in registers
// (at the default 32-reg cap ptxas spills w[32] to local, serializing on LDL).
// ---------------------------------------------------------------------------
__global__ void __launch_bounds__(512, 1) prep_kernel(
        const float* __restrict__ Wk, const float* __restrict__ bk,
        const float* __restrict__ Wq, const float* __restrict__ bq,
        const float* __restrict__ W) {
    const int side = blockIdx.x >> 4;        // 0 = K, 1 = Q
    const int a    = blockIdx.x & 15;
    const float* Wx = side ? Wq : Wk;
    const float* bx = side ? bq : bk;

    const int t  = threadIdx.x;
    const int d  = t & 127;
    const int ep = t >> 7;                   // e-partition 0..3

    // Prefetch: 32 independent LDGs in flight (one DRAM round trip).
    float w[32];
#pragma unroll
    for (int i = 0; i < 32; i++)
        w[i] = Wx[(ep * 32 + i) * D_ + d];

    __shared__ float Wsh[IDM_ * RR_];        // W[a] : [128,3]
    __shared__ float red[4][IDM_ * RR_];     // partial sums

    for (int i = t; i < IDM_ * RR_; i += 512) Wsh[i] = W[a * IDM_ * RR_ + i];
    __syncthreads();

    float a0 = 0.f, a1 = 0.f, a2 = 0.f;
#pragma unroll
    for (int i = 0; i < 32; i++) {
        int e = ep * 32 + i;
        a0 = fmaf(w[i], Wsh[e * 3 + 0], a0);
        a1 = fmaf(w[i], Wsh[e * 3 + 1], a1);
        a2 = fmaf(w[i], Wsh[e * 3 + 2], a2);
    }
    red[ep][d * 3 + 0] = a0;
    red[ep][d * 3 + 1] = a1;
    red[ep][d * 3 + 2] = a2;
    __syncthreads();

    if (ep == 0) {
        int base = a * (IDM_ * RR_) + d * RR_;
#pragma unroll
        for (int r = 0; r < RR_; r++) {
            int i = d * 3 + r;
            g_M[side][base + r] = red[0][i] + red[1][i] + red[2][i] + red[3][i];
        }
    }

    if (t < 32) {   // bias fold on warp 0
        float c0 = 0.f, c1 = 0.f, c2 = 0.f;
#pragma unroll
        for (int e = t; e < IDM_; e += 32) {
            float b = bx[e];
            c0 = fmaf(b, Wsh[e * 3 + 0], c0);
            c1 = fmaf(b, Wsh[e * 3 + 1], c1);
            c2 = fmaf(b, Wsh[e * 3 + 2], c2);
        }
#pragma unroll
        for (int o = 16; o > 0; o >>= 1) {
            c0 += __shfl_xor_sync(0xffffffffu, c0, o);
            c1 += __shfl_xor_sync(0xffffffffu, c1, o);
            c2 += __shfl_xor_sync(0xffffffffu, c2, o);
        }
        if (t == 0) {
            g_c[side][a * RR_ + 0] = c0;
            g_c[side][a * RR_ + 1] = c1;
            g_c[side][a * RR_ + 2] = c2;
        }
    }
}

// ---------------------------------------------------------------------------
// Kernel 2 (R12 version, proven): hash codes, 4 rows per warp (MLP=4).
// ---------------------------------------------------------------------------
__global__ void __launch_bounds__(256) code_kernel(
        const float* __restrict__ K, const float* __restrict__ Q) {
    int warp = (blockIdx.x * blockDim.x + threadIdx.x) >> 5;
    int lane = threadIdx.x & 31;
    int grow0 = warp * 4;                    // 4 consecutive rows, same (side,a)
    int which = (grow0 >= A_ * SK_) ? 1 : 0;
    int row0  = which ? (grow0 - A_ * SK_) : grow0;
    int a     = row0 >> 11;

    const float* X = which ? Q : K;
    const float4* Xv = reinterpret_cast<const float4*>(X);
    float4 x0 = Xv[(row0 + 0) * (D_ / 4) + lane];
    float4 x1 = Xv[(row0 + 1) * (D_ / 4) + lane];
    float4 x2 = Xv[(row0 + 2) * (D_ / 4) + lane];
    float4 x3 = Xv[(row0 + 3) * (D_ / 4) + lane];

    const float* M = &g_M[which][a * (IDM_ * RR_) + lane * 12];
    float4 m0 = *reinterpret_cast<const float4*>(M);
    float4 m1 = *reinterpret_cast<const float4*>(M + 4);
    float4 m2 = *reinterpret_cast<const float4*>(M + 8);

    float p00 = x0.x * m0.x + x0.y * m0.w + x0.z * m1.z + x0.w * m2.y;
    float p01 = x0.x * m0.y + x0.y * m1.x + x0.z * m1.w + x0.w * m2.z;
    float p02 = x0.x * m0.z + x0.y * m1.y + x0.z * m2.x + x0.w * m2.w;
    float p10 = x1.x * m0.x + x1.y * m0.w + x1.z * m1.z + x1.w * m2.y;
    float p11 = x1.x * m0.y + x1.y * m1.x + x1.z * m1.w + x1.w * m2.z;
    float p12 = x1.x * m0.z + x1.y * m1.y + x1.z * m2.x + x1.w * m2.w;
    float p20 = x2.x * m0.x + x2.y * m0.w + x2.z * m1.z + x2.w * m2.y;
    float p21 = x2.x * m0.y + x2.y * m1.x + x2.z * m1.w + x2.w * m2.z;
    float p22 = x2.x * m0.z + x2.y * m1.y + x2.z * m2.x + x2.w * m2.w;
    float p30 = x3.x * m0.x + x3.y * m0.w + x3.z * m1.z + x3.w * m2.y;
    float p31 = x3.x * m0.y + x3.y * m1.x + x3.z * m1.w + x3.w * m2.z;
    float p32 = x3.x * m0.z + x3.y * m1.y + x3.z * m2.x + x3.w * m2.w;

#pragma unroll
    for (int o = 16; o > 0; o >>= 1) {       // 12 interleaved chains
        p00 += __shfl_xor_sync(0xffffffffu, p00, o);
        p10 += __shfl_xor_sync(0xffffffffu, p10, o);
        p20 += __shfl_xor_sync(0xffffffffu, p20, o);
        p30 += __shfl_xor_sync(0xffffffffu, p30, o);
        p01 += __shfl_xor_sync(0xffffffffu, p01, o);
        p11 += __shfl_xor_sync(0xffffffffu, p11, o);
        p21 += __shfl_xor_sync(0xffffffffu, p21, o);
        p31 += __shfl_xor_sync(0xffffffffu, p31, o);
        p02 += __shfl_xor_sync(0xffffffffu, p02, o);
        p12 += __shfl_xor_sync(0xffffffffu, p12, o);
        p22 += __shfl_xor_sync(0xffffffffu, p22, o);
        p32 += __shfl_xor_sync(0xffffffffu, p32, o);
    }

    if (lane < 4) {
        float s0 = (lane == 0) ? p00 : (lane == 1) ? p10 : (lane == 2) ? p20 : p30;
        float s1 = (lane == 0) ? p01 : (lane == 1) ? p11 : (lane == 2) ? p21 : p31;
        float s2 = (lane == 0) ? p02 : (lane == 1) ? p12 : (lane == 2) ? p22 : p32;
        const float* c = &g_c[which][a * RR_];
        float scale = which ? 1.0f : (1.0f / 3.0f);   // fold /R into Kc
        float v0 = tanhf((s0 + c[0]) * 0.1f) * scale;
        float v1 = tanhf((s1 + c[1]) * 0.1f) * scale;
        float v2 = tanhf((s2 + c[2]) * 0.1f) * scale;
        g_code[which][row0 + lane] = make_float4(v0, v1, v2, 0.f);
    }
}

// ---------------------------------------------------------------------------
// Kernel 3 (unchanged, near write-roofline): 16 t-rows x 1024 s-cols.
// ---------------------------------------------------------------------------
__device__ __forceinline__ float pc_fn(const float4 q, const float4 k) {
    float x  = fmaf(q.x, k.x, fmaf(q.y, k.y, q.z * k.z));      // Kc already /3
    float t  = x * x;
    float sg = fmaf(x, fmaf(t, -2.0833333e-5f, 0.025f), 0.5f); // sigmoid(x/10)
    return x * sg;
}

__global__ void __launch_bounds__(256) pc_kernel(float* __restrict__ out) {
    const int a     = blockIdx.z;
    const int tbase = blockIdx.y * 16;
    const int sbase = blockIdx.x * 1024;
    const int tid   = threadIdx.x;

    __shared__ float4 qc_sh[16];
    if (tid < 16)
        qc_sh[tid] = g_code[1][a * SQ_ + tbase + tid];

    const float4* kc = &g_code[0][a * SK_ + sbase + tid * 4];
    const float4 k0 = kc[0];
    const float4 k1 = kc[1];
    const float4 k2 = kc[2];
    const float4 k3 = kc[3];
    __syncthreads();

    float* obase = out + ((size_t)(a * SQ_ + tbase)) * SK_ + (size_t)(sbase + tid * 4);
#pragma unroll 4
    for (int j = 0; j < 16; j++) {
        const float4 q = qc_sh[j];        // broadcast LDS
        float4 o;
        o.x = pc_fn(q, k0);
        o.y = pc_fn(q, k1);
        o.z = pc_fn(q, k2);
        o.w = pc_fn(q, k3);
        *reinterpret_cast<float4*>(obase + (size_t)j * SK_) = o;
    }
}

// ---------------------------------------------------------------------------
// Launch
// ---------------------------------------------------------------------------
extern "C" void kernel_launch(void* const* d_in, const int* in_sizes, int n_in,
                              void* d_out, int out_size) {
    const float* K  = (const float*)d_in[0];
    const float* Q  = (const float*)d_in[1];
    const float* Wk = (const float*)d_in[2];
    const float* bk = (const float*)d_in[3];
    const float* Wq = (const float*)d_in[4];
    const float* bq = (const float*)d_in[5];
    const float* W  = (const float*)d_in[6];
    float* out = (float*)d_out;

    prep_kernel<<<2 * A_, 512>>>(Wk, bk, Wq, bq, W);
    code_kernel<<<(2 * A_ * SK_) / 32, 256>>>(K, Q);
    pc_kernel<<<dim3(SK_ / 1024, SQ_ / 16, A_), 256>>>(out);
}

// round 14
// speedup vs baseline: 1.8744x; 1.0893x over previous
#include <cuda_runtime.h>
#include <math.h>

// Problem constants (fixed by the dataset)
#define A_   16
#define SK_  2048
#define SQ_  2048
#define D_   128
#define IDM_ 128
#define RR_  3
// T_ANNEAL = 10, t_ANNEAL = 0

// ---------------------------------------------------------------------------
// Scratch (device globals — no allocation allowed)
// ---------------------------------------------------------------------------
__device__ float  g_M[2][A_ * IDM_ * RR_];   // folded projections
__device__ float  g_c[2][A_ * RR_];          // folded bias projections
__device__ float4 g_code[2][A_ * SK_];       // [0] = Kc/3, [1] = Qc

// ---------------------------------------------------------------------------
// Kernel 1 (R13 version, at launch/ramp floor): fold Wk/Wq + bias via W[a].
// ---------------------------------------------------------------------------
__global__ void __launch_bounds__(512, 1) prep_kernel(
        const float* __restrict__ Wk, const float* __restrict__ bk,
        const float* __restrict__ Wq, const float* __restrict__ bq,
        const float* __restrict__ W) {
    const int side = blockIdx.x >> 4;        // 0 = K, 1 = Q
    const int a    = blockIdx.x & 15;
    const float* Wx = side ? Wq : Wk;
    const float* bx = side ? bq : bk;

    const int t  = threadIdx.x;
    const int d  = t & 127;
    const int ep = t >> 7;                   // e-partition 0..3

    float w[32];
#pragma unroll
    for (int i = 0; i < 32; i++)
        w[i] = Wx[(ep * 32 + i) * D_ + d];

    __shared__ float Wsh[IDM_ * RR_];        // W[a] : [128,3]
    __shared__ float red[4][IDM_ * RR_];     // partial sums

    for (int i = t; i < IDM_ * RR_; i += 512) Wsh[i] = W[a * IDM_ * RR_ + i];
    __syncthreads();

    float a0 = 0.f, a1 = 0.f, a2 = 0.f;
#pragma unroll
    for (int i = 0; i < 32; i++) {
        int e = ep * 32 + i;
        a0 = fmaf(w[i], Wsh[e * 3 + 0], a0);
        a1 = fmaf(w[i], Wsh[e * 3 + 1], a1);
        a2 = fmaf(w[i], Wsh[e * 3 + 2], a2);
    }
    red[ep][d * 3 + 0] = a0;
    red[ep][d * 3 + 1] = a1;
    red[ep][d * 3 + 2] = a2;
    __syncthreads();

    if (ep == 0) {
        int base = a * (IDM_ * RR_) + d * RR_;
#pragma unroll
        for (int r = 0; r < RR_; r++) {
            int i = d * 3 + r;
            g_M[side][base + r] = red[0][i] + red[1][i] + red[2][i] + red[3][i];
        }
    }

    if (t < 32) {   // bias fold on warp 0
        float c0 = 0.f, c1 = 0.f, c2 = 0.f;
#pragma unroll
        for (int e = t; e < IDM_; e += 32) {
            float b = bx[e];
            c0 = fmaf(b, Wsh[e * 3 + 0], c0);
            c1 = fmaf(b, Wsh[e * 3 + 1], c1);
            c2 = fmaf(b, Wsh[e * 3 + 2], c2);
        }
#pragma unroll
        for (int o = 16; o > 0; o >>= 1) {
            c0 += __shfl_xor_sync(0xffffffffu, c0, o);
            c1 += __shfl_xor_sync(0xffffffffu, c1, o);
            c2 += __shfl_xor_sync(0xffffffffu, c2, o);
        }
        if (t == 0) {
            g_c[side][a * RR_ + 0] = c0;
            g_c[side][a * RR_ + 1] = c1;
            g_c[side][a * RR_ + 2] = c2;
        }
    }
}

// ---------------------------------------------------------------------------
// Kernel 2: hash codes, 8 rows per warp (MLP=8 on the X loads).
// 24 interleaved shuffle chains; lanes 0..7 write one row each.
// Grid: 1024 blocks x 256 threads = 8192 warps x 8 rows = 65536 rows.
// __launch_bounds__(256, 2): ~75 live regs must NOT spill (R12 lesson).
// ---------------------------------------------------------------------------
__global__ void __launch_bounds__(256, 2) code_kernel(
        const float* __restrict__ K, const float* __restrict__ Q) {
    int warp = (blockIdx.x * blockDim.x + threadIdx.x) >> 5;
    int lane = threadIdx.x & 31;
    int grow0 = warp * 8;                    // 8 consecutive rows, same (side,a)
    int which = (grow0 >= A_ * SK_) ? 1 : 0;
    int row0  = which ? (grow0 - A_ * SK_) : grow0;
    int a     = row0 >> 11;

    const float* X = which ? Q : K;
    const float4* Xv = reinterpret_cast<const float4*>(X);
    float4 x[8];
#pragma unroll
    for (int i = 0; i < 8; i++)
        x[i] = Xv[(row0 + i) * (D_ / 4) + lane];

    const float* M = &g_M[which][a * (IDM_ * RR_) + lane * 12];
    float4 m0 = *reinterpret_cast<const float4*>(M);
    float4 m1 = *reinterpret_cast<const float4*>(M + 4);
    float4 m2 = *reinterpret_cast<const float4*>(M + 8);

    float p0[8], p1[8], p2[8];
#pragma unroll
    for (int i = 0; i < 8; i++) {
        p0[i] = x[i].x * m0.x + x[i].y * m0.w + x[i].z * m1.z + x[i].w * m2.y;
        p1[i] = x[i].x * m0.y + x[i].y * m1.x + x[i].z * m1.w + x[i].w * m2.z;
        p2[i] = x[i].x * m0.z + x[i].y * m1.y + x[i].z * m2.x + x[i].w * m2.w;
    }

#pragma unroll
    for (int o = 16; o > 0; o >>= 1) {       // 24 interleaved chains
#pragma unroll
        for (int i = 0; i < 8; i++) {
            p0[i] += __shfl_xor_sync(0xffffffffu, p0[i], o);
            p1[i] += __shfl_xor_sync(0xffffffffu, p1[i], o);
            p2[i] += __shfl_xor_sync(0xffffffffu, p2[i], o);
        }
    }

    // Full sums live in every lane; lanes 0..7 each finish one row.
    if (lane < 8) {
        float s0, s1, s2;
#pragma unroll
        for (int i = 0; i < 8; i++)
            if (lane == i) { s0 = p0[i]; s1 = p1[i]; s2 = p2[i]; }
        const float* c = &g_c[which][a * RR_];
        float scale = which ? 1.0f : (1.0f / 3.0f);   // fold /R into Kc
        float v0 = tanhf((s0 + c[0]) * 0.1f) * scale;
        float v1 = tanhf((s1 + c[1]) * 0.1f) * scale;
        float v2 = tanhf((s2 + c[2]) * 0.1f) * scale;
        g_code[which][row0 + lane] = make_float4(v0, v1, v2, 0.f);
    }
}

// ---------------------------------------------------------------------------
// Kernel 3: main pass, 16 t-rows x 1024 s-cols; streaming stores (__stcs):
// output (256MB) is never re-read and is 2x L2 — avoid write-allocate churn.
// ---------------------------------------------------------------------------
__device__ __forceinline__ float pc_fn(const float4 q, const float4 k) {
    float x  = fmaf(q.x, k.x, fmaf(q.y, k.y, q.z * k.z));      // Kc already /3
    float t  = x * x;
    float sg = fmaf(x, fmaf(t, -2.0833333e-5f, 0.025f), 0.5f); // sigmoid(x/10)
    return x * sg;
}

__global__ void __launch_bounds__(256) pc_kernel(float* __restrict__ out) {
    const int a     = blockIdx.z;
    const int tbase = blockIdx.y * 16;
    const int sbase = blockIdx.x * 1024;
    const int tid   = threadIdx.x;

    __shared__ float4 qc_sh[16];
    if (tid < 16)
        qc_sh[tid] = g_code[1][a * SQ_ + tbase + tid];

    const float4* kc = &g_code[0][a * SK_ + sbase + tid * 4];
    const float4 k0 = kc[0];
    const float4 k1 = kc[1];
    const float4 k2 = kc[2];
    const float4 k3 = kc[3];
    __syncthreads();

    float* obase = out + ((size_t)(a * SQ_ + tbase)) * SK_ + (size_t)(sbase + tid * 4);
#pragma unroll 4
    for (int j = 0; j < 16; j++) {
        const float4 q = qc_sh[j];        // broadcast LDS
        float4 o;
        o.x = pc_fn(q, k0);
        o.y = pc_fn(q, k1);
        o.z = pc_fn(q, k2);
        o.w = pc_fn(q, k3);
        __stcs(reinterpret_cast<float4*>(obase + (size_t)j * SK_), o);
    }
}

// ---------------------------------------------------------------------------
// Launch
// ---------------------------------------------------------------------------
extern "C" void kernel_launch(void* const* d_in, const int* in_sizes, int n_in,
                              void* d_out, int out_size) {
    const float* K  = (const float*)d_in[0];
    const float* Q  = (const float*)d_in[1];
    const float* Wk = (const float*)d_in[2];
    const float* bk = (const float*)d_in[3];
    const float* Wq = (const float*)d_in[4];
    const float* bq = (const float*)d_in[5];
    const float* W  = (const float*)d_in[6];
    float* out = (float*)d_out;

    prep_kernel<<<2 * A_, 512>>>(Wk, bk, Wq, bq, W);
    code_kernel<<<(2 * A_ * SK_) / 64, 256>>>(K, Q);
    pc_kernel<<<dim3(SK_ / 1024, SQ_ / 16, A_), 256>>>(out);
}